// round 14
// baseline (speedup 1.0000x reference)
#include <cuda_runtime.h>
#include <cuda_fp16.h>
#include <math.h>
#include <float.h>

// Problem constants (fixed shapes for this benchmark)
#define cN 20000
#define cE 320000
#define cMAXIT 10

// ---------------- device scratch (no allocations allowed) ----------------
__device__ __align__(16) float g_ZP [(size_t)2*cN*256];    // piecewise-eval of [z0;z1]@Ba + [0,bmsg]
__device__ __align__(16) float g_P1 [(size_t)cN*128];
__device__ __align__(16) float g_P2 [(size_t)cN*128];
// fp16 2-way splits, layout [row][256] = [split0(128) | split1(128)]
__device__ __align__(16) __half g_as[(size_t)cN*256];
__device__ __align__(16) __half g_hs[(size_t)cN*256];
// transposed weight splits: [out_col][256] = [w(128) | resid(128)] along K
__device__ __align__(16) __half g_BhT[256*256];
__device__ __align__(16) __half g_WoT[128*256];
// fp32 packed encoder-side weight [zdim(128)][col(256)] = [W1a | W2a]
__device__ __align__(16) float g_Baf[128*256];
// piecewise-linear ZP machinery
__device__ float g_knots[2][129];          // [var][0]=-inf sentinel, [1..128] sorted knots
__device__ int   g_korder[2][128];
__device__ __align__(16) float2 g_coef[(size_t)2*129*256];   // (u,v) per var/interval/col
__device__ float g_a1[cN], g_a2[cN];
__device__ unsigned g_mx2[2][cN];          // double-buffered per-node max(alpha) bits
__device__ unsigned g_mxd[cN];
__device__ int g_cnt[cN], g_ptr[cN], g_fill[cN], g_csrc[cE], g_best[cN];
__device__ int g_total;

// ---------------- helpers ----------------
static __device__ __forceinline__ unsigned smem_u32(const void* p) {
    unsigned a;
    asm("{ .reg .u64 t; cvta.to.shared.u64 t, %1; cvt.u32.u64 %0, t; }" : "=r"(a) : "l"(p));
    return a;
}
// split pair (x,y) into two half2 words (main, residual)
static __device__ __forceinline__ void sph(float x, float y, unsigned& w0, unsigned& w1) {
    __half hx = __float2half_rn(x), hy = __float2half_rn(y);
    float rx = x - __half2float(hx), ry = y - __half2float(hy);
    __half2 a = __halves2half2(hx, hy);
    w0 = *reinterpret_cast<unsigned*>(&a);
    __half2 b = __floats2half2_rn(rx, ry);
    w1 = *reinterpret_cast<unsigned*>(&b);
}

#define LDMX4(r0, r1, r2, r3, addr) \
    asm volatile("ldmatrix.sync.aligned.m8n8.x4.shared.b16 {%0,%1,%2,%3}, [%4];" \
                 : "=r"(r0), "=r"(r1), "=r"(r2), "=r"(r3) : "r"(addr))
#define MMA16816(c, a, b0v, b1v) \
    asm volatile("mma.sync.aligned.m16n8k16.row.col.f32.f16.f16.f32 " \
                 "{%0,%1,%2,%3}, {%4,%5,%6,%7}, {%8,%9}, {%0,%1,%2,%3};" \
                 : "+f"((c)[0]), "+f"((c)[1]), "+f"((c)[2]), "+f"((c)[3]) \
                 : "r"((a)[0]), "r"((a)[1]), "r"((a)[2]), "r"((a)[3]), \
                   "r"(b0v), "r"(b1v))

// ---------------- small utility kernels ----------------
__global__ void k_init(int n, int e) {
    int i = blockIdx.x * blockDim.x + threadIdx.x;
    if (i < n) {
        g_cnt[i] = 0; g_mx2[0][i] = 0u; g_mx2[1][i] = 0u;
        g_mxd[i] = 0u; g_best[i] = e;
    }
    if (i == 0) g_total = 0;
}

// weight pack: Baf fp32 + transposed fp16 splits for Bh/Wo
__global__ void k_pack(const float* __restrict__ W1, const float* __restrict__ W2,
                       const float* __restrict__ Wout) {
    int idx = blockIdx.x * blockDim.x + threadIdx.x;
    if (idx < 128 * 256) {
        int k = idx >> 8, j = idx & 255;  // k = input dim, j = output col
        float a = (j < 128) ? W1[k*128 + j]       : W2[k*128 + (j-128)];
        float b = (j < 128) ? W1[(128+k)*128 + j] : W2[(128+k)*128 + (j-128)];
        g_Baf[idx] = a;                    // [k][j] with j contiguous
        int o = j * 256 + k;
        __half hb = __float2half_rn(b);
        g_BhT[o] = hb; g_BhT[o + 128] = __float2half_rn(b - __half2float(hb));
    }
    if (idx < 128 * 128) {
        int k = idx >> 7, j = idx & 127;
        float w = Wout[k*128 + j];
        int o = j * 256 + k;
        __half hw = __float2half_rn(w);
        g_WoT[o] = hw; g_WoT[o + 128] = __float2half_rn(w - __half2float(hw));
    }
}

// sort relu breakpoints per variant: x_j = -b_j/w_j (w==0 -> +inf, toggle no-op)
__global__ void k_sort(const float* __restrict__ We, const float* __restrict__ be) {
    int v = blockIdx.x, j = threadIdx.x;   // 2 blocks x 128 threads
    __shared__ float xs[128];
    float w = We[j];
    float b = be[j] + (v ? We[128 + j] : 0.f);
    float x = (w != 0.f) ? (-b / w) : FLT_MAX;
    xs[j] = x;
    __syncthreads();
    int rank = 0;
    for (int k = 0; k < 128; k++) {
        float xk = xs[k];
        rank += (xk < x) || (xk == x && k < j);
    }
    g_knots[v][rank + 1] = x;
    g_korder[v][rank] = j;
    if (j == 0) g_knots[v][0] = -FLT_MAX;
}

// sweep sorted knots, accumulating per-interval affine coefficients in double
__global__ void k_coef(const float* __restrict__ We, const float* __restrict__ be,
                       const float* __restrict__ bmsg) {
    int v = blockIdx.x, c = threadIdx.x;   // 2 blocks x 256 threads (one per col)
    __shared__ int ord[128];
    __shared__ float ws[128], bs[128];
    if (c < 128) {
        ws[c] = We[c];
        bs[c] = be[c] + (v ? We[128 + c] : 0.f);
        ord[c] = g_korder[v][c];
    }
    __syncthreads();
    double u = 0.0, vv = (c >= 128) ? (double)bmsg[c - 128] : 0.0;
    // initial active set at pos = -inf
    for (int j = 0; j < 128; j++) {
        float w = ws[j], b = bs[j];
        bool act = (w < 0.f) || (w == 0.f && b > 0.f);
        if (act) {
            double a = (double)g_Baf[j * 256 + c];
            u += (double)w * a; vv += (double)b * a;
        }
    }
    g_coef[((size_t)v * 129) * 256 + c] = make_float2((float)u, (float)vv);
    for (int s = 0; s < 128; s++) {
        int j = ord[s];
        float w = ws[j], b = bs[j];
        if (w != 0.f) {
            double a = (double)g_Baf[j * 256 + c];
            if (w > 0.f) { u += (double)w * a; vv += (double)b * a; }
            else         { u -= (double)w * a; vv -= (double)b * a; }
        }
        g_coef[((size_t)v * 129 + s + 1) * 256 + c] = make_float2((float)u, (float)vv);
    }
}

// evaluate ZP rows (one warp per (variant,node)); fuses it-0 combine into P1/P2
__global__ void k_zp(const float* __restrict__ pos, const float* __restrict__ s, int n) {
    __shared__ float kn[2][128];
    int tid = threadIdx.x;
    {
        int v = tid >> 7, j = tid & 127;
        kn[v][j] = g_knots[v][j + 1];
    }
    __syncthreads();
    int gw = blockIdx.x * 8 + (tid >> 5);
    int lane = tid & 31;
    if (gw >= 2 * n) return;
    int var = (gw >= n) ? 1 : 0;
    int node = gw - var * n;
    float p = pos[node];
    int lo = 0, hi = 128;
    while (lo < hi) { int mid = (lo + hi) >> 1; if (kn[var][mid] <= p) lo = mid + 1; else hi = mid; }
    const float2* cf = g_coef + ((size_t)var * 129 + lo) * 256;
    int c0 = lane * 8;
    float o[8];
    #pragma unroll
    for (int q = 0; q < 8; q++) {
        float2 uv = cf[c0 + q];
        o[q] = fmaf(p, uv.x, uv.y);
    }
    float* zp = g_ZP + ((size_t)var * n + node) * 256 + c0;
    *(float4*)zp       = make_float4(o[0], o[1], o[2], o[3]);
    *(float4*)(zp + 4) = make_float4(o[4], o[5], o[6], o[7]);
    // fused iteration-0 combine: selected variant's halves -> P1/P2
    if (((s[node] > 0.5f) ? 1 : 0) == var) {
        float* d = (lane < 16) ? (g_P1 + (size_t)node * 128 + c0)
                               : (g_P2 + (size_t)node * 128 + (c0 - 128));
        *(float4*)d       = make_float4(o[0], o[1], o[2], o[3]);
        *(float4*)(d + 4) = make_float4(o[4], o[5], o[6], o[7]);
    }
}

// ---------------- tensor-core GEMM (fp32 via fp16 2-split, 3 products) -------
// D[128,128] = A[m0:,K=128] @ B^T[n0:,K=128] per CTA via mma.sync m16n8k16.
// Products (a1,b0),(a0,b1),(a0,b0); a1*b1 dropped (<2^-22 rel).
// A resident in smem [128][SA]; B streamed in BK=64 chunks, double-buffered.
// Modes: 1: P{1,2} = D + ZP[reach(mxsel)]   (grid=(.,2))
//        2: h = relu(D + bout); write h-splits + a1/a2 = h.Wdec halves
#define SA 264
#define SB 72
#define SMEM_DYN (128*SA*2 + 2*128*SB*2)   // 67584 + 36864 = 104448

__global__ void __launch_bounds__(256, 2) k_mma(
    const __half* __restrict__ A, const __half* __restrict__ B,
    int M, int mode,
    const float* __restrict__ ZP, const unsigned* __restrict__ mxsel,
    float* __restrict__ P1o, float* __restrict__ P2o,
    const float* __restrict__ bout, const float* __restrict__ Wdec,
    __half* __restrict__ hs,
    float* __restrict__ a1, float* __restrict__ a2, int Nnodes)
{
    extern __shared__ char smem[];
    __half* As = (__half*)smem;            // [128][SA]
    __half* Bs = As + 128 * SA;            // [2][128][SB]
    unsigned sA = smem_u32(As), sB0 = smem_u32(Bs);
    int tid = threadIdx.x, wid = tid >> 5, lane = tid & 31;
    int m0 = blockIdx.x * 128, n0 = blockIdx.y * 128;
    int warp_m = wid & 1, warp_n = wid >> 1;
    int wm0 = warp_m * 64, wn0 = warp_n * 32;

    // ---- A into smem ----
    {
        int row = tid >> 1, off = (tid & 1) * 128;
        int gr = m0 + row;
        const uint4* gA = (const uint4*)(A + (size_t)gr * 256 + off);
        uint4* shA = (uint4*)(As + row * SA + off);
        #pragma unroll
        for (int q = 0; q < 16; q++) {
            uint4 va = make_uint4(0u, 0u, 0u, 0u);
            if (gr < M) va = gA[q];
            shA[q] = va;
        }
    }

    // ---- B chunk schedule: idx -> (product, k-half); products (a1,b0),(a0,b1),(a0,b0)
    const int pa_l[3] = {128, 0, 0};
    const int pb_l[3] = {0, 128, 0};
    int br = tid >> 1, bq = tid & 1;          // B loader: row(col), which 32-half block
    uint4 breg[4];
    {
        const uint4* gB = (const uint4*)(B + (size_t)(n0 + br) * 256 + pb_l[0] + bq * 32);
        breg[0] = gB[0]; breg[1] = gB[1]; breg[2] = gB[2]; breg[3] = gB[3];
        uint4* shB = (uint4*)(Bs + br * SB + bq * 32);
        shB[0] = breg[0]; shB[1] = breg[1]; shB[2] = breg[2]; shB[3] = breg[3];
    }
    __syncthreads();

    float acc[4][4][4];
    #pragma unroll
    for (int i = 0; i < 4; i++)
        #pragma unroll
        for (int j = 0; j < 4; j++)
            #pragma unroll
            for (int r = 0; r < 4; r++) acc[i][j][r] = 0.f;

    int a_row = wm0 + (lane & 15);
    int a_colx = ((lane >> 4) << 3);
    int b_row = wn0 + (lane & 7) + (((lane >> 4) & 1) << 3);
    int b_colx = (((lane >> 3) & 1) << 3);

    for (int idx = 0; idx < 6; idx++) {
        int p = idx >> 1, c = idx & 1;
        if (idx + 1 < 6) {   // prefetch next B chunk into regs (overlaps compute)
            int pn = (idx + 1) >> 1, cn = (idx + 1) & 1;
            const uint4* gB = (const uint4*)(B + (size_t)(n0 + br) * 256 + pb_l[pn] + cn * 64 + bq * 32);
            breg[0] = gB[0]; breg[1] = gB[1]; breg[2] = gB[2]; breg[3] = gB[3];
        }
        unsigned sBc = sB0 + (unsigned)(idx & 1) * 128 * SB * 2;
        int acol0 = pa_l[p] + c * 64;
        #pragma unroll
        for (int ks = 0; ks < 4; ks++) {
            int k0 = ks * 16;
            unsigned a[4][4], b[2][4];
            #pragma unroll
            for (int mf = 0; mf < 4; mf++) {
                unsigned ad = sA + (unsigned)((a_row + mf * 16) * SA + acol0 + k0 + a_colx) * 2;
                LDMX4(a[mf][0], a[mf][1], a[mf][2], a[mf][3], ad);
            }
            #pragma unroll
            for (int nf2 = 0; nf2 < 2; nf2++) {
                unsigned bd = sBc + (unsigned)((b_row + nf2 * 16) * SB + k0 + b_colx) * 2;
                LDMX4(b[nf2][0], b[nf2][1], b[nf2][2], b[nf2][3], bd);
            }
            #pragma unroll
            for (int mf = 0; mf < 4; mf++) {
                #pragma unroll
                for (int nf = 0; nf < 4; nf++) {
                    unsigned* bp = &b[nf >> 1][(nf & 1) * 2];
                    MMA16816(acc[mf][nf], a[mf], bp[0], bp[1]);
                }
            }
        }
        if (idx + 1 < 6) {
            uint4* shB = (uint4*)(Bs + (size_t)((idx + 1) & 1) * 128 * SB + br * SB + bq * 32);
            shB[0] = breg[0]; shB[1] = breg[1]; shB[2] = breg[2]; shB[3] = breg[3];
        }
        __syncthreads();
    }

    // ---- epilogue ----
    int trow = lane >> 2, tcol2 = (lane & 3) * 2;

    if (mode == 2) {
        float* pr = (float*)Bs;                // reuse B buffers: [2][4][128]
        #pragma unroll
        for (int mf = 0; mf < 4; mf++) {
            #pragma unroll
            for (int rr = 0; rr < 2; rr++) {
                int lrow = wm0 + mf * 16 + trow + rr * 8;
                int grow = m0 + lrow;
                float s1 = 0.f, s2 = 0.f;
                #pragma unroll
                for (int nf = 0; nf < 4; nf++) {
                    int gc = wn0 + nf * 8 + tcol2;
                    float d0 = acc[mf][nf][rr * 2 + 0];
                    float d1 = acc[mf][nf][rr * 2 + 1];
                    float h0 = fmaxf(d0 + bout[gc],     0.f);
                    float h1 = fmaxf(d1 + bout[gc + 1], 0.f);
                    s1 += h0 * Wdec[gc] + h1 * Wdec[gc + 1];
                    s2 += h0 * Wdec[128 + gc] + h1 * Wdec[128 + gc + 1];
                    if (grow < M) {
                        unsigned w0, w1;
                        sph(h0, h1, w0, w1);
                        *(unsigned*)(hs + (size_t)grow * 256 + gc)       = w0;
                        *(unsigned*)(hs + (size_t)grow * 256 + 128 + gc) = w1;
                    }
                }
                s1 += __shfl_xor_sync(0xffffffffu, s1, 1);
                s1 += __shfl_xor_sync(0xffffffffu, s1, 2);
                s2 += __shfl_xor_sync(0xffffffffu, s2, 1);
                s2 += __shfl_xor_sync(0xffffffffu, s2, 2);
                if ((lane & 3) == 0) {
                    pr[warp_n * 128 + lrow]       = s1;
                    pr[512 + warp_n * 128 + lrow] = s2;
                }
            }
        }
        __syncthreads();
        if (tid < 128 && m0 + tid < M) {
            float s1 = ((pr[tid] + pr[128 + tid]) + pr[256 + tid]) + pr[384 + tid];
            float s2 = ((pr[512 + tid] + pr[640 + tid]) + pr[768 + tid]) + pr[896 + tid];
            a1[m0 + tid] = s1;
            a2[m0 + tid] = s2;
        }
    } else { // mode 1
        float* dst = (blockIdx.y == 0) ? P1o : P2o;
        #pragma unroll
        for (int mf = 0; mf < 4; mf++) {
            #pragma unroll
            for (int rr = 0; rr < 2; rr++) {
                int grow = m0 + wm0 + mf * 16 + trow + rr * 8;
                if (grow < M) {
                    bool r1 = (__uint_as_float(mxsel[grow]) >= 0.4f);
                    size_t zoff = (r1 ? (size_t)Nnodes * 256 : 0)
                                + (size_t)grow * 256 + n0;
                    #pragma unroll
                    for (int nf = 0; nf < 4; nf++) {
                        int col = wn0 + nf * 8 + tcol2;
                        float2 z = *(const float2*)(ZP + zoff + col);
                        float2 o = make_float2(acc[mf][nf][rr * 2 + 0] + z.x,
                                               acc[mf][nf][rr * 2 + 1] + z.y);
                        *(float2*)(dst + (size_t)grow * 128 + col) = o;
                    }
                }
            }
        }
    }
}

// ---------------- CSR build over dst (parallel reservation, no scan) ---------
__global__ void k_count(const int* __restrict__ dst, int e) {
    int idx = blockIdx.x * blockDim.x + threadIdx.x;
    if (idx < e) atomicAdd(&g_cnt[dst[idx]], 1);
}
__global__ void k_reserve(int n) {
    int i = blockIdx.x * blockDim.x + threadIdx.x;
    if (i < n) {
        int c = g_cnt[i];
        int p = atomicAdd(&g_total, c);
        g_ptr[i] = p;
        g_fill[i] = p;
    }
}
__global__ void k_fill(const int* __restrict__ src, const int* __restrict__ dst, int e) {
    int idx = blockIdx.x * blockDim.x + threadIdx.x;
    if (idx < e) {
        int p = atomicAdd(&g_fill[dst[idx]], 1);
        g_csrc[p] = src[idx];
    }
}

// ---------------- per-iteration kernels ----------------
// one warp per destination node; relu(max(P1[src]) + P2c[dst]) exact (monotone hoist)
// output: agg fp16 splits [i][256]; also zeros the next alpha max-buffer entry.
__global__ void k_agg(int n, unsigned* __restrict__ mxzero) {
    int gw = (blockIdx.x * blockDim.x + threadIdx.x) >> 5;
    int lane = threadIdx.x & 31;
    if (gw >= n) return;
    if (lane == 0) mxzero[gw] = 0u;
    float4 c = ((const float4*)g_P2)[(size_t)gw * 32 + lane];
    int beg = g_ptr[gw], end = beg + g_cnt[gw];
    float4 m = make_float4(-FLT_MAX, -FLT_MAX, -FLT_MAX, -FLT_MAX);
    int t = beg;
    for (; t + 3 < end; t += 4) {          // 4-deep MLP (max is order-exact)
        int s0 = g_csrc[t], s1 = g_csrc[t+1], s2 = g_csrc[t+2], s3 = g_csrc[t+3];
        float4 p0 = ((const float4*)g_P1)[(size_t)s0 * 32 + lane];
        float4 p1 = ((const float4*)g_P1)[(size_t)s1 * 32 + lane];
        float4 p2 = ((const float4*)g_P1)[(size_t)s2 * 32 + lane];
        float4 p3 = ((const float4*)g_P1)[(size_t)s3 * 32 + lane];
        m.x = fmaxf(m.x, fmaxf(fmaxf(p0.x, p1.x), fmaxf(p2.x, p3.x)));
        m.y = fmaxf(m.y, fmaxf(fmaxf(p0.y, p1.y), fmaxf(p2.y, p3.y)));
        m.z = fmaxf(m.z, fmaxf(fmaxf(p0.z, p1.z), fmaxf(p2.z, p3.z)));
        m.w = fmaxf(m.w, fmaxf(fmaxf(p0.w, p1.w), fmaxf(p2.w, p3.w)));
    }
    for (; t < end; t++) {
        int s0 = g_csrc[t];
        float4 p0 = ((const float4*)g_P1)[(size_t)s0 * 32 + lane];
        m.x = fmaxf(m.x, p0.x); m.y = fmaxf(m.y, p0.y);
        m.z = fmaxf(m.z, p0.z); m.w = fmaxf(m.w, p0.w);
    }
    float4 o;
    if (end > beg) {
        o.x = fmaxf(m.x + c.x, 0.f); o.y = fmaxf(m.y + c.y, 0.f);
        o.z = fmaxf(m.z + c.z, 0.f); o.w = fmaxf(m.w + c.w, 0.f);
    } else {
        o = make_float4(0.f, 0.f, 0.f, 0.f);
    }
    size_t base = (size_t)gw * 256 + lane * 4;
    unsigned wa0, wa1, wb0, wb1;
    sph(o.x, o.y, wa0, wa1);
    sph(o.z, o.w, wb0, wb1);
    *(uint2*)(g_as + base)       = make_uint2(wa0, wb0);
    *(uint2*)(g_as + base + 128) = make_uint2(wa1, wb1);
}

__device__ __forceinline__ float sigmoidf_(float x) {
    if (x >= 0.f) return 1.f / (1.f + expf(-x));
    float e = expf(x);
    return e / (1.f + e);
}

__global__ void k_alpha(const int* __restrict__ src, const int* __restrict__ dst,
                        const float* __restrict__ bdec, float* __restrict__ preds,
                        unsigned* __restrict__ mx, int e, int isLast) {
    int idx = blockIdx.x * blockDim.x + threadIdx.x;
    if (idx < e) {
        int si = src[idx], di = dst[idx];
        float lg = g_a1[si] + g_a2[di] + bdec[0];
        float al = sigmoidf_(lg);
        preds[idx] = al;
        unsigned u = __float_as_uint(al);   // alpha > 0 -> bit order == float order
        atomicMax(&mx[si], u);
        atomicMax(&mx[di], u);
        if (isLast) atomicMax(&g_mxd[di], u);
    }
}

__global__ void k_winner(const int* __restrict__ dst, const float* __restrict__ lastpred, int e) {
    int idx = blockIdx.x * blockDim.x + threadIdx.x;
    if (idx < e) {
        int d = dst[idx];
        if (__float_as_uint(lastpred[idx]) == g_mxd[d]) atomicMin(&g_best[d], idx);
    }
}

__global__ void k_final(const int* __restrict__ src, const unsigned* __restrict__ mxfin,
                        float* __restrict__ out_reach,
                        float* __restrict__ out_par, int n, int e) {
    int i = blockIdx.x * blockDim.x + threadIdx.x;
    if (i < n) {
        out_reach[i] = (__uint_as_float(mxfin[i]) >= 0.4f) ? 1.f : 0.f;
        int b = g_best[i];
        out_par[i] = (float)(b < e ? src[b] : i);
    }
}

// ---------------- host launcher (graph-capturable) ----------------
extern "C" void kernel_launch(void* const* d_in, const int* in_sizes, int n_in,
                              void* d_out, int out_size) {
    const float* pos  = (const float*)d_in[0];
    const float* s    = (const float*)d_in[1];
    const int*   ei   = (const int*)  d_in[2];
    const float* Wenc = (const float*)d_in[3];
    const float* benc = (const float*)d_in[4];
    const float* W1   = (const float*)d_in[5];
    const float* W2   = (const float*)d_in[6];
    const float* bmsg = (const float*)d_in[7];
    const float* Wout = (const float*)d_in[8];
    const float* bout = (const float*)d_in[9];
    const float* Wdec = (const float*)d_in[10];
    const float* bdec = (const float*)d_in[11];

    int N = in_sizes[0];
    int E = in_sizes[2] / 2;
    if (N > cN || E > cE || N <= 0 || E <= 0) return;
    int MAXIT = (out_size - 2 * N) / E;
    if (MAXIT < 1) MAXIT = 1;
    if (MAXIT > cMAXIT) MAXIT = cMAXIT;

    const int* srcA = ei;
    const int* dstA = ei + E;
    float* out = (float*)d_out;

    cudaFuncSetAttribute(k_mma, cudaFuncAttributeMaxDynamicSharedMemorySize, SMEM_DYN);

    void *pZP, *pP1, *pP2, *pa1, *pa2, *pmx2;
    void *pas, *phs, *pBhT, *pWoT;
    cudaGetSymbolAddress(&pZP,   g_ZP);
    cudaGetSymbolAddress(&pP1,   g_P1);
    cudaGetSymbolAddress(&pP2,   g_P2);
    cudaGetSymbolAddress(&pa1,   g_a1);
    cudaGetSymbolAddress(&pa2,   g_a2);
    cudaGetSymbolAddress(&pmx2,  g_mx2);
    cudaGetSymbolAddress(&pas,  g_as);
    cudaGetSymbolAddress(&phs,  g_hs);
    cudaGetSymbolAddress(&pBhT, g_BhT);
    cudaGetSymbolAddress(&pWoT, g_WoT);

    unsigned* mxbuf0 = (unsigned*)pmx2;
    unsigned* mxbuf1 = mxbuf0 + cN;

    // ---- setup ----
    k_init<<<(N + 255) / 256, 256>>>(N, E);
    k_pack<<<128, 256>>>(W1, W2, Wout);
    k_sort<<<2, 128>>>(Wenc, benc);
    k_coef<<<2, 256>>>(Wenc, benc, bmsg);
    k_zp<<<(2 * N + 7) / 8, 256>>>(pos, s, N);   // ZP + fused it-0 combine
    k_count<<<(E + 255) / 256, 256>>>(dstA, E);
    k_reserve<<<(N + 255) / 256, 256>>>(N);
    k_fill<<<(E + 255) / 256, 256>>>(srcA, dstA, E);

    // ---- iterations ----
    for (int it = 0; it < MAXIT; ++it) {
        if (it > 0) {
            // P1,P2 = h @ Bh + ZP[reach from mx buffer (it-1)&1] — mode 1
            dim3 g((N + 127) / 128, 2);
            k_mma<<<g, 256, SMEM_DYN>>>(
                (const __half*)phs, (const __half*)pBhT,
                N, 1,
                (const float*)pZP,
                ((it - 1) & 1) ? mxbuf1 : mxbuf0,
                (float*)pP1, (float*)pP2,
                nullptr, nullptr, nullptr,
                nullptr, nullptr, N);
        }
        // agg also zeroes the buffer alpha(it+1) will use = buf[(it+1)&1]
        k_agg<<<(N + 7) / 8, 256>>>(N, ((it + 1) & 1) ? mxbuf1 : mxbuf0);
        {   // h = relu(agg @ Wout + bout); h-splits + a1/a2 — mode 2
            dim3 g((N + 127) / 128, 1);
            k_mma<<<g, 256, SMEM_DYN>>>(
                (const __half*)pas, (const __half*)pWoT,
                N, 2,
                nullptr, nullptr,
                nullptr, nullptr,
                bout, Wdec,
                (__half*)phs,
                (float*)pa1, (float*)pa2, N);
        }
        k_alpha<<<(E + 255) / 256, 256>>>(srcA, dstA, bdec, out + (size_t)it * E,
                                          (it & 1) ? mxbuf1 : mxbuf0,
                                          E, (it == MAXIT - 1) ? 1 : 0);
    }

    // ---- parents + outputs ----
    k_winner<<<(E + 255) / 256, 256>>>(dstA, out + (size_t)(MAXIT - 1) * E, E);
    k_final<<<(N + 255) / 256, 256>>>(srcA,
                                      ((MAXIT - 1) & 1) ? mxbuf1 : mxbuf0,
                                      out + (size_t)MAXIT * E,
                                      out + (size_t)MAXIT * E + N, N, E);
}

// round 16
// speedup vs baseline: 1.1524x; 1.1524x over previous
#include <cuda_runtime.h>
#include <cuda_fp16.h>
#include <math.h>
#include <float.h>

// Problem constants (fixed shapes for this benchmark)
#define cN 20000
#define cE 320000
#define cMAXIT 10

// ---------------- device scratch (no allocations allowed) ----------------
__device__ __align__(16) float g_ZP [(size_t)2*cN*256];    // piecewise-eval of [z0;z1]@Ba + [0,bmsg]
__device__ __align__(16) float g_P1 [(size_t)cN*128];
__device__ __align__(16) float g_P2 [(size_t)cN*128];
// fp16 2-way splits, layout [row][256] = [split0(128) | split1(128)]
__device__ __align__(16) __half g_as[(size_t)cN*256];
__device__ __align__(16) __half g_hs[(size_t)cN*256];
// transposed weight splits: [out_col][256] = [w(128) | resid(128)] along K
__device__ __align__(16) __half g_BhT[256*256];
__device__ __align__(16) __half g_WoT[128*256];
// fp32 packed encoder-side weight [zdim(128)][col(256)] = [W1a | W2a]
__device__ __align__(16) float g_Baf[128*256];
// piecewise-linear ZP machinery
__device__ float g_knots[2][129];          // [var][0]=-inf sentinel, [1..128] sorted knots
__device__ int   g_korder[2][128];
__device__ __align__(16) float2 g_coef[(size_t)2*129*256];   // (u,v) per var/interval/col
__device__ float g_a1[cN], g_a2[cN];
__device__ unsigned g_mx2[2][cN];          // double-buffered per-node max(alpha) bits
__device__ unsigned g_mxd[cN];
__device__ int g_cnt[cN], g_ptr[cN], g_fill[cN], g_csrc[cE], g_best[cN];
__device__ int g_total;

// ---------------- helpers ----------------
static __device__ __forceinline__ unsigned smem_u32(const void* p) {
    unsigned a;
    asm("{ .reg .u64 t; cvta.to.shared.u64 t, %1; cvt.u32.u64 %0, t; }" : "=r"(a) : "l"(p));
    return a;
}
// split pair (x,y) into two half2 words (main, residual)
static __device__ __forceinline__ void sph(float x, float y, unsigned& w0, unsigned& w1) {
    __half hx = __float2half_rn(x), hy = __float2half_rn(y);
    float rx = x - __half2float(hx), ry = y - __half2float(hy);
    __half2 a = __halves2half2(hx, hy);
    w0 = *reinterpret_cast<unsigned*>(&a);
    __half2 b = __floats2half2_rn(rx, ry);
    w1 = *reinterpret_cast<unsigned*>(&b);
}

#define LDMX4(r0, r1, r2, r3, addr) \
    asm volatile("ldmatrix.sync.aligned.m8n8.x4.shared.b16 {%0,%1,%2,%3}, [%4];" \
                 : "=r"(r0), "=r"(r1), "=r"(r2), "=r"(r3) : "r"(addr))
#define MMA16816(c, a, b0v, b1v) \
    asm volatile("mma.sync.aligned.m16n8k16.row.col.f32.f16.f16.f32 " \
                 "{%0,%1,%2,%3}, {%4,%5,%6,%7}, {%8,%9}, {%0,%1,%2,%3};" \
                 : "+f"((c)[0]), "+f"((c)[1]), "+f"((c)[2]), "+f"((c)[3]) \
                 : "r"((a)[0]), "r"((a)[1]), "r"((a)[2]), "r"((a)[3]), \
                   "r"(b0v), "r"(b1v))

// ---------------- small utility kernels ----------------
__global__ void k_init(int n, int e) {
    int i = blockIdx.x * blockDim.x + threadIdx.x;
    if (i < n) {
        g_cnt[i] = 0; g_mx2[0][i] = 0u; g_mx2[1][i] = 0u;
        g_mxd[i] = 0u; g_best[i] = e;
    }
    if (i == 0) g_total = 0;
}

// weight pack: Baf fp32 + transposed fp16 splits for Bh/Wo
__global__ void k_pack(const float* __restrict__ W1, const float* __restrict__ W2,
                       const float* __restrict__ Wout) {
    int idx = blockIdx.x * blockDim.x + threadIdx.x;
    if (idx < 128 * 256) {
        int k = idx >> 8, j = idx & 255;  // k = input dim, j = output col
        float a = (j < 128) ? W1[k*128 + j]       : W2[k*128 + (j-128)];
        float b = (j < 128) ? W1[(128+k)*128 + j] : W2[(128+k)*128 + (j-128)];
        g_Baf[idx] = a;                    // [k][j] with j contiguous
        int o = j * 256 + k;
        __half hb = __float2half_rn(b);
        g_BhT[o] = hb; g_BhT[o + 128] = __float2half_rn(b - __half2float(hb));
    }
    if (idx < 128 * 128) {
        int k = idx >> 7, j = idx & 127;
        float w = Wout[k*128 + j];
        int o = j * 256 + k;
        __half hw = __float2half_rn(w);
        g_WoT[o] = hw; g_WoT[o + 128] = __float2half_rn(w - __half2float(hw));
    }
}

// sort relu breakpoints per variant: x_j = -b_j/w_j (w==0 -> +inf, toggle no-op)
__global__ void k_sort(const float* __restrict__ We, const float* __restrict__ be) {
    int v = blockIdx.x, j = threadIdx.x;   // 2 blocks x 128 threads
    __shared__ float xs[128];
    float w = We[j];
    float b = be[j] + (v ? We[128 + j] : 0.f);
    float x = (w != 0.f) ? (-b / w) : FLT_MAX;
    xs[j] = x;
    __syncthreads();
    int rank = 0;
    for (int k = 0; k < 128; k++) {
        float xk = xs[k];
        rank += (xk < x) || (xk == x && k < j);
    }
    g_knots[v][rank + 1] = x;
    g_korder[v][rank] = j;
    if (j == 0) g_knots[v][0] = -FLT_MAX;
}

// per-interval affine coefficients via parallel warp scan (double precision).
// grid (2, 32), block 256 = 8 warps; warp handles column c = blockIdx.y*8 + wid.
__global__ void k_coef(const float* __restrict__ We, const float* __restrict__ be,
                       const float* __restrict__ bmsg) {
    int v = blockIdx.x;
    int wid = threadIdx.x >> 5, lane = threadIdx.x & 31;
    int c = blockIdx.y * 8 + wid;
    __shared__ float ws[128], bs[128];
    __shared__ int ord[128];
    if (threadIdx.x < 128) {
        ws[threadIdx.x] = We[threadIdx.x];
        bs[threadIdx.x] = be[threadIdx.x] + (v ? We[128 + threadIdx.x] : 0.f);
        ord[threadIdx.x] = g_korder[v][threadIdx.x];
    }
    __syncthreads();

    // initial active set at pos = -inf (lane-strided partial + warp reduce)
    double u0 = 0.0, v0 = 0.0;
    #pragma unroll
    for (int t = 0; t < 4; t++) {
        int j = lane + t * 32;
        float w = ws[j], b = bs[j];
        if ((w < 0.f) || (w == 0.f && b > 0.f)) {
            double a = (double)g_Baf[j * 256 + c];
            u0 += (double)w * a; v0 += (double)b * a;
        }
    }
    #pragma unroll
    for (int o = 16; o > 0; o >>= 1) {
        u0 += __shfl_xor_sync(0xffffffffu, u0, o);
        v0 += __shfl_xor_sync(0xffffffffu, v0, o);
    }
    v0 += (c >= 128) ? (double)bmsg[c - 128] : 0.0;

    // lane handles 4 sorted steps: local deltas + inclusive prefix
    double du[4], dv[4];
    double su = 0.0, sv = 0.0;
    #pragma unroll
    for (int t = 0; t < 4; t++) {
        int s = lane * 4 + t;
        int j = ord[s];
        float w = ws[j], b = bs[j];
        if (w != 0.f) {
            double a = (double)g_Baf[j * 256 + c];
            if (w > 0.f) { su += (double)w * a; sv += (double)b * a; }
            else         { su -= (double)w * a; sv -= (double)b * a; }
        }
        du[t] = su; dv[t] = sv;
    }
    // inclusive warp scan of lane totals, then exclusive = inclusive - own
    double eu = su, ev = sv;
    #pragma unroll
    for (int o = 1; o < 32; o <<= 1) {
        double tu = __shfl_up_sync(0xffffffffu, eu, o);
        double tv = __shfl_up_sync(0xffffffffu, ev, o);
        if (lane >= o) { eu += tu; ev += tv; }
    }
    double xu = (eu - su) + u0, xv = (ev - sv) + v0;

    if (lane == 0)
        g_coef[((size_t)v * 129) * 256 + c] = make_float2((float)u0, (float)v0);
    #pragma unroll
    for (int t = 0; t < 4; t++) {
        int s = lane * 4 + t;
        g_coef[((size_t)v * 129 + s + 1) * 256 + c] =
            make_float2((float)(xu + du[t]), (float)(xv + dv[t]));
    }
}

// evaluate ZP rows (one warp per (variant,node)); fuses it-0 combine into P1/P2
__global__ void k_zp(const float* __restrict__ pos, const float* __restrict__ s, int n) {
    __shared__ float kn[2][128];
    int tid = threadIdx.x;
    {
        int v = tid >> 7, j = tid & 127;
        kn[v][j] = g_knots[v][j + 1];
    }
    __syncthreads();
    int gw = blockIdx.x * 8 + (tid >> 5);
    int lane = tid & 31;
    if (gw >= 2 * n) return;
    int var = (gw >= n) ? 1 : 0;
    int node = gw - var * n;
    float p = pos[node];
    int lo = 0, hi = 128;
    while (lo < hi) { int mid = (lo + hi) >> 1; if (kn[var][mid] <= p) lo = mid + 1; else hi = mid; }
    const float2* cf = g_coef + ((size_t)var * 129 + lo) * 256;
    int c0 = lane * 8;
    float o[8];
    #pragma unroll
    for (int q = 0; q < 8; q++) {
        float2 uv = cf[c0 + q];
        o[q] = fmaf(p, uv.x, uv.y);
    }
    float* zp = g_ZP + ((size_t)var * n + node) * 256 + c0;
    *(float4*)zp       = make_float4(o[0], o[1], o[2], o[3]);
    *(float4*)(zp + 4) = make_float4(o[4], o[5], o[6], o[7]);
    // fused iteration-0 combine: selected variant's halves -> P1/P2
    if (((s[node] > 0.5f) ? 1 : 0) == var) {
        float* d = (lane < 16) ? (g_P1 + (size_t)node * 128 + c0)
                               : (g_P2 + (size_t)node * 128 + (c0 - 128));
        *(float4*)d       = make_float4(o[0], o[1], o[2], o[3]);
        *(float4*)(d + 4) = make_float4(o[4], o[5], o[6], o[7]);
    }
}

// ---------------- tensor-core GEMM (fp32 via fp16 2-split, 3 products) -------
// D[128,128] = A[m0:,K=128] @ B^T[n0:,K=128] per CTA via mma.sync m16n8k16.
// Products (a1,b0),(a0,b1),(a0,b0); a1*b1 dropped (<2^-22 rel).
// A resident in smem [128][SA]; B streamed in BK=64 chunks, double-buffered.
// Modes: 1: P{1,2} = D + ZP[reach(mxsel)]   (grid=(.,2))
//        2: h = relu(D + bout); write h-splits + a1/a2 = h.Wdec halves
#define SA 264
#define SB 72
#define SMEM_DYN (128*SA*2 + 2*128*SB*2)   // 67584 + 36864 = 104448

__global__ void __launch_bounds__(256, 2) k_mma(
    const __half* __restrict__ A, const __half* __restrict__ B,
    int M, int mode,
    const float* __restrict__ ZP, const unsigned* __restrict__ mxsel,
    float* __restrict__ P1o, float* __restrict__ P2o,
    const float* __restrict__ bout, const float* __restrict__ Wdec,
    __half* __restrict__ hs,
    float* __restrict__ a1, float* __restrict__ a2, int Nnodes)
{
    extern __shared__ char smem[];
    __half* As = (__half*)smem;            // [128][SA]
    __half* Bs = As + 128 * SA;            // [2][128][SB]
    unsigned sA = smem_u32(As), sB0 = smem_u32(Bs);
    int tid = threadIdx.x, wid = tid >> 5, lane = tid & 31;
    int m0 = blockIdx.x * 128, n0 = blockIdx.y * 128;
    int warp_m = wid & 1, warp_n = wid >> 1;
    int wm0 = warp_m * 64, wn0 = warp_n * 32;

    // ---- A into smem ----
    {
        int row = tid >> 1, off = (tid & 1) * 128;
        int gr = m0 + row;
        const uint4* gA = (const uint4*)(A + (size_t)gr * 256 + off);
        uint4* shA = (uint4*)(As + row * SA + off);
        #pragma unroll
        for (int q = 0; q < 16; q++) {
            uint4 va = make_uint4(0u, 0u, 0u, 0u);
            if (gr < M) va = gA[q];
            shA[q] = va;
        }
    }

    // ---- B chunk schedule: idx -> (product, k-half); products (a1,b0),(a0,b1),(a0,b0)
    const int pa_l[3] = {128, 0, 0};
    const int pb_l[3] = {0, 128, 0};
    int br = tid >> 1, bq = tid & 1;          // B loader: row(col), which 32-half block
    uint4 breg[4];
    {
        const uint4* gB = (const uint4*)(B + (size_t)(n0 + br) * 256 + pb_l[0] + bq * 32);
        breg[0] = gB[0]; breg[1] = gB[1]; breg[2] = gB[2]; breg[3] = gB[3];
        uint4* shB = (uint4*)(Bs + br * SB + bq * 32);
        shB[0] = breg[0]; shB[1] = breg[1]; shB[2] = breg[2]; shB[3] = breg[3];
    }
    __syncthreads();

    float acc[4][4][4];
    #pragma unroll
    for (int i = 0; i < 4; i++)
        #pragma unroll
        for (int j = 0; j < 4; j++)
            #pragma unroll
            for (int r = 0; r < 4; r++) acc[i][j][r] = 0.f;

    int a_row = wm0 + (lane & 15);
    int a_colx = ((lane >> 4) << 3);
    int b_row = wn0 + (lane & 7) + (((lane >> 4) & 1) << 3);
    int b_colx = (((lane >> 3) & 1) << 3);

    for (int idx = 0; idx < 6; idx++) {
        int p = idx >> 1, c = idx & 1;
        if (idx + 1 < 6) {   // prefetch next B chunk into regs (overlaps compute)
            int pn = (idx + 1) >> 1, cn = (idx + 1) & 1;
            const uint4* gB = (const uint4*)(B + (size_t)(n0 + br) * 256 + pb_l[pn] + cn * 64 + bq * 32);
            breg[0] = gB[0]; breg[1] = gB[1]; breg[2] = gB[2]; breg[3] = gB[3];
        }
        unsigned sBc = sB0 + (unsigned)(idx & 1) * 128 * SB * 2;
        int acol0 = pa_l[p] + c * 64;
        #pragma unroll
        for (int ks = 0; ks < 4; ks++) {
            int k0 = ks * 16;
            unsigned a[4][4], b[2][4];
            #pragma unroll
            for (int mf = 0; mf < 4; mf++) {
                unsigned ad = sA + (unsigned)((a_row + mf * 16) * SA + acol0 + k0 + a_colx) * 2;
                LDMX4(a[mf][0], a[mf][1], a[mf][2], a[mf][3], ad);
            }
            #pragma unroll
            for (int nf2 = 0; nf2 < 2; nf2++) {
                unsigned bd = sBc + (unsigned)((b_row + nf2 * 16) * SB + k0 + b_colx) * 2;
                LDMX4(b[nf2][0], b[nf2][1], b[nf2][2], b[nf2][3], bd);
            }
            #pragma unroll
            for (int mf = 0; mf < 4; mf++) {
                #pragma unroll
                for (int nf = 0; nf < 4; nf++) {
                    unsigned* bp = &b[nf >> 1][(nf & 1) * 2];
                    MMA16816(acc[mf][nf], a[mf], bp[0], bp[1]);
                }
            }
        }
        if (idx + 1 < 6) {
            uint4* shB = (uint4*)(Bs + (size_t)((idx + 1) & 1) * 128 * SB + br * SB + bq * 32);
            shB[0] = breg[0]; shB[1] = breg[1]; shB[2] = breg[2]; shB[3] = breg[3];
        }
        __syncthreads();
    }

    // ---- epilogue ----
    int trow = lane >> 2, tcol2 = (lane & 3) * 2;

    if (mode == 2) {
        float* pr = (float*)Bs;                // reuse B buffers: [2][4][128]
        #pragma unroll
        for (int mf = 0; mf < 4; mf++) {
            #pragma unroll
            for (int rr = 0; rr < 2; rr++) {
                int lrow = wm0 + mf * 16 + trow + rr * 8;
                int grow = m0 + lrow;
                float s1 = 0.f, s2 = 0.f;
                #pragma unroll
                for (int nf = 0; nf < 4; nf++) {
                    int gc = wn0 + nf * 8 + tcol2;
                    float d0 = acc[mf][nf][rr * 2 + 0];
                    float d1 = acc[mf][nf][rr * 2 + 1];
                    float h0 = fmaxf(d0 + bout[gc],     0.f);
                    float h1 = fmaxf(d1 + bout[gc + 1], 0.f);
                    s1 += h0 * Wdec[gc] + h1 * Wdec[gc + 1];
                    s2 += h0 * Wdec[128 + gc] + h1 * Wdec[128 + gc + 1];
                    if (grow < M) {
                        unsigned w0, w1;
                        sph(h0, h1, w0, w1);
                        *(unsigned*)(hs + (size_t)grow * 256 + gc)       = w0;
                        *(unsigned*)(hs + (size_t)grow * 256 + 128 + gc) = w1;
                    }
                }
                s1 += __shfl_xor_sync(0xffffffffu, s1, 1);
                s1 += __shfl_xor_sync(0xffffffffu, s1, 2);
                s2 += __shfl_xor_sync(0xffffffffu, s2, 1);
                s2 += __shfl_xor_sync(0xffffffffu, s2, 2);
                if ((lane & 3) == 0) {
                    pr[warp_n * 128 + lrow]       = s1;
                    pr[512 + warp_n * 128 + lrow] = s2;
                }
            }
        }
        __syncthreads();
        if (tid < 128 && m0 + tid < M) {
            float s1 = ((pr[tid] + pr[128 + tid]) + pr[256 + tid]) + pr[384 + tid];
            float s2 = ((pr[512 + tid] + pr[640 + tid]) + pr[768 + tid]) + pr[896 + tid];
            a1[m0 + tid] = s1;
            a2[m0 + tid] = s2;
        }
    } else { // mode 1
        float* dst = (blockIdx.y == 0) ? P1o : P2o;
        #pragma unroll
        for (int mf = 0; mf < 4; mf++) {
            #pragma unroll
            for (int rr = 0; rr < 2; rr++) {
                int grow = m0 + wm0 + mf * 16 + trow + rr * 8;
                if (grow < M) {
                    bool r1 = (__uint_as_float(mxsel[grow]) >= 0.4f);
                    size_t zoff = (r1 ? (size_t)Nnodes * 256 : 0)
                                + (size_t)grow * 256 + n0;
                    #pragma unroll
                    for (int nf = 0; nf < 4; nf++) {
                        int col = wn0 + nf * 8 + tcol2;
                        float2 z = *(const float2*)(ZP + zoff + col);
                        float2 o = make_float2(acc[mf][nf][rr * 2 + 0] + z.x,
                                               acc[mf][nf][rr * 2 + 1] + z.y);
                        *(float2*)(dst + (size_t)grow * 128 + col) = o;
                    }
                }
            }
        }
    }
}

// ---------------- CSR build over dst (parallel reservation, no scan) ---------
__global__ void k_count(const int* __restrict__ dst, int e) {
    int idx = blockIdx.x * blockDim.x + threadIdx.x;
    if (idx < e) atomicAdd(&g_cnt[dst[idx]], 1);
}
__global__ void k_reserve(int n) {
    int i = blockIdx.x * blockDim.x + threadIdx.x;
    if (i < n) {
        int c = g_cnt[i];
        int p = atomicAdd(&g_total, c);
        g_ptr[i] = p;
        g_fill[i] = p;
    }
}
__global__ void k_fill(const int* __restrict__ src, const int* __restrict__ dst, int e) {
    int idx = blockIdx.x * blockDim.x + threadIdx.x;
    if (idx < e) {
        int p = atomicAdd(&g_fill[dst[idx]], 1);
        g_csrc[p] = src[idx];
    }
}

// ---------------- per-iteration kernels ----------------
// one warp per destination node; relu(max(P1[src]) + P2c[dst]) exact (monotone hoist)
// output: agg fp16 splits [i][256]; also zeros the next alpha max-buffer entry.
__global__ void k_agg(int n, unsigned* __restrict__ mxzero) {
    int gw = (blockIdx.x * blockDim.x + threadIdx.x) >> 5;
    int lane = threadIdx.x & 31;
    if (gw >= n) return;
    if (lane == 0) mxzero[gw] = 0u;
    float4 c = ((const float4*)g_P2)[(size_t)gw * 32 + lane];
    int beg = g_ptr[gw], end = beg + g_cnt[gw];
    float4 m = make_float4(-FLT_MAX, -FLT_MAX, -FLT_MAX, -FLT_MAX);
    int t = beg;
    for (; t + 3 < end; t += 4) {          // 4-deep MLP (max is order-exact)
        int s0 = g_csrc[t], s1 = g_csrc[t+1], s2 = g_csrc[t+2], s3 = g_csrc[t+3];
        float4 p0 = ((const float4*)g_P1)[(size_t)s0 * 32 + lane];
        float4 p1 = ((const float4*)g_P1)[(size_t)s1 * 32 + lane];
        float4 p2 = ((const float4*)g_P1)[(size_t)s2 * 32 + lane];
        float4 p3 = ((const float4*)g_P1)[(size_t)s3 * 32 + lane];
        m.x = fmaxf(m.x, fmaxf(fmaxf(p0.x, p1.x), fmaxf(p2.x, p3.x)));
        m.y = fmaxf(m.y, fmaxf(fmaxf(p0.y, p1.y), fmaxf(p2.y, p3.y)));
        m.z = fmaxf(m.z, fmaxf(fmaxf(p0.z, p1.z), fmaxf(p2.z, p3.z)));
        m.w = fmaxf(m.w, fmaxf(fmaxf(p0.w, p1.w), fmaxf(p2.w, p3.w)));
    }
    for (; t < end; t++) {
        int s0 = g_csrc[t];
        float4 p0 = ((const float4*)g_P1)[(size_t)s0 * 32 + lane];
        m.x = fmaxf(m.x, p0.x); m.y = fmaxf(m.y, p0.y);
        m.z = fmaxf(m.z, p0.z); m.w = fmaxf(m.w, p0.w);
    }
    float4 o;
    if (end > beg) {
        o.x = fmaxf(m.x + c.x, 0.f); o.y = fmaxf(m.y + c.y, 0.f);
        o.z = fmaxf(m.z + c.z, 0.f); o.w = fmaxf(m.w + c.w, 0.f);
    } else {
        o = make_float4(0.f, 0.f, 0.f, 0.f);
    }
    size_t base = (size_t)gw * 256 + lane * 4;
    unsigned wa0, wa1, wb0, wb1;
    sph(o.x, o.y, wa0, wa1);
    sph(o.z, o.w, wb0, wb1);
    *(uint2*)(g_as + base)       = make_uint2(wa0, wb0);
    *(uint2*)(g_as + base + 128) = make_uint2(wa1, wb1);
}

__device__ __forceinline__ float sigmoidf_(float x) {
    if (x >= 0.f) return 1.f / (1.f + expf(-x));
    float e = expf(x);
    return e / (1.f + e);
}

__global__ void k_alpha(const int* __restrict__ src, const int* __restrict__ dst,
                        const float* __restrict__ bdec, float* __restrict__ preds,
                        unsigned* __restrict__ mx, int e, int isLast) {
    int idx = blockIdx.x * blockDim.x + threadIdx.x;
    if (idx < e) {
        int si = src[idx], di = dst[idx];
        float lg = g_a1[si] + g_a2[di] + bdec[0];
        float al = sigmoidf_(lg);
        preds[idx] = al;
        unsigned u = __float_as_uint(al);   // alpha > 0 -> bit order == float order
        atomicMax(&mx[si], u);
        atomicMax(&mx[di], u);
        if (isLast) atomicMax(&g_mxd[di], u);
    }
}

__global__ void k_winner(const int* __restrict__ dst, const float* __restrict__ lastpred, int e) {
    int idx = blockIdx.x * blockDim.x + threadIdx.x;
    if (idx < e) {
        int d = dst[idx];
        if (__float_as_uint(lastpred[idx]) == g_mxd[d]) atomicMin(&g_best[d], idx);
    }
}

__global__ void k_final(const int* __restrict__ src, const unsigned* __restrict__ mxfin,
                        float* __restrict__ out_reach,
                        float* __restrict__ out_par, int n, int e) {
    int i = blockIdx.x * blockDim.x + threadIdx.x;
    if (i < n) {
        out_reach[i] = (__uint_as_float(mxfin[i]) >= 0.4f) ? 1.f : 0.f;
        int b = g_best[i];
        out_par[i] = (float)(b < e ? src[b] : i);
    }
}

// ---------------- host launcher (graph-capturable) ----------------
extern "C" void kernel_launch(void* const* d_in, const int* in_sizes, int n_in,
                              void* d_out, int out_size) {
    const float* pos  = (const float*)d_in[0];
    const float* s    = (const float*)d_in[1];
    const int*   ei   = (const int*)  d_in[2];
    const float* Wenc = (const float*)d_in[3];
    const float* benc = (const float*)d_in[4];
    const float* W1   = (const float*)d_in[5];
    const float* W2   = (const float*)d_in[6];
    const float* bmsg = (const float*)d_in[7];
    const float* Wout = (const float*)d_in[8];
    const float* bout = (const float*)d_in[9];
    const float* Wdec = (const float*)d_in[10];
    const float* bdec = (const float*)d_in[11];

    int N = in_sizes[0];
    int E = in_sizes[2] / 2;
    if (N > cN || E > cE || N <= 0 || E <= 0) return;
    int MAXIT = (out_size - 2 * N) / E;
    if (MAXIT < 1) MAXIT = 1;
    if (MAXIT > cMAXIT) MAXIT = cMAXIT;

    const int* srcA = ei;
    const int* dstA = ei + E;
    float* out = (float*)d_out;

    cudaFuncSetAttribute(k_mma, cudaFuncAttributeMaxDynamicSharedMemorySize, SMEM_DYN);

    void *pZP, *pP1, *pP2, *pa1, *pa2, *pmx2;
    void *pas, *phs, *pBhT, *pWoT;
    cudaGetSymbolAddress(&pZP,   g_ZP);
    cudaGetSymbolAddress(&pP1,   g_P1);
    cudaGetSymbolAddress(&pP2,   g_P2);
    cudaGetSymbolAddress(&pa1,   g_a1);
    cudaGetSymbolAddress(&pa2,   g_a2);
    cudaGetSymbolAddress(&pmx2,  g_mx2);
    cudaGetSymbolAddress(&pas,  g_as);
    cudaGetSymbolAddress(&phs,  g_hs);
    cudaGetSymbolAddress(&pBhT, g_BhT);
    cudaGetSymbolAddress(&pWoT, g_WoT);

    unsigned* mxbuf0 = (unsigned*)pmx2;
    unsigned* mxbuf1 = mxbuf0 + cN;

    // ---- setup ----
    k_init<<<(N + 255) / 256, 256>>>(N, E);
    k_pack<<<128, 256>>>(W1, W2, Wout);
    k_sort<<<2, 128>>>(Wenc, benc);
    k_coef<<<dim3(2, 32), 256>>>(Wenc, benc, bmsg);
    k_zp<<<(2 * N + 7) / 8, 256>>>(pos, s, N);   // ZP + fused it-0 combine
    k_count<<<(E + 255) / 256, 256>>>(dstA, E);
    k_reserve<<<(N + 255) / 256, 256>>>(N);
    k_fill<<<(E + 255) / 256, 256>>>(srcA, dstA, E);

    // ---- iterations ----
    for (int it = 0; it < MAXIT; ++it) {
        if (it > 0) {
            // P1,P2 = h @ Bh + ZP[reach from mx buffer (it-1)&1] — mode 1
            dim3 g((N + 127) / 128, 2);
            k_mma<<<g, 256, SMEM_DYN>>>(
                (const __half*)phs, (const __half*)pBhT,
                N, 1,
                (const float*)pZP,
                ((it - 1) & 1) ? mxbuf1 : mxbuf0,
                (float*)pP1, (float*)pP2,
                nullptr, nullptr, nullptr,
                nullptr, nullptr, N);
        }
        // agg also zeroes the buffer alpha(it+1) will use = buf[(it+1)&1]
        k_agg<<<(N + 7) / 8, 256>>>(N, ((it + 1) & 1) ? mxbuf1 : mxbuf0);
        {   // h = relu(agg @ Wout + bout); h-splits + a1/a2 — mode 2
            dim3 g((N + 127) / 128, 1);
            k_mma<<<g, 256, SMEM_DYN>>>(
                (const __half*)pas, (const __half*)pWoT,
                N, 2,
                nullptr, nullptr,
                nullptr, nullptr,
                bout, Wdec,
                (__half*)phs,
                (float*)pa1, (float*)pa2, N);
        }
        k_alpha<<<(E + 255) / 256, 256>>>(srcA, dstA, bdec, out + (size_t)it * E,
                                          (it & 1) ? mxbuf1 : mxbuf0,
                                          E, (it == MAXIT - 1) ? 1 : 0);
    }

    // ---- parents + outputs ----
    k_winner<<<(E + 255) / 256, 256>>>(dstA, out + (size_t)(MAXIT - 1) * E, E);
    k_final<<<(N + 255) / 256, 256>>>(srcA,
                                      ((MAXIT - 1) & 1) ? mxbuf1 : mxbuf0,
                                      out + (size_t)MAXIT * E,
                                      out + (size_t)MAXIT * E + N, N, E);
}